// round 15
// baseline (speedup 1.0000x reference)
#include <cuda_runtime.h>

#define NMAX 8192

// Scratch — zero-initialized at module load; contrib_kernel restores accumulator
// zeros after every call so graph replays see a clean state. g_contrib is
// overwritten every call, never cleaned.
__device__ int      g_cntpack[2][NMAX];   // low 16: cnt, high 16: pos_cnt
__device__ float    g_sumexp[2][NMAX];    // sum of exp(out[i]) over mask
__device__ float    g_poslog[2][NMAX];    // sum of out[i] over mask & pos
__device__ float    g_contrib[NMAX];      // per-column contribution (overwritten)
__device__ float    g_res;                // cross-block partial sum
__device__ unsigned g_done;               // block-completion counter

// .cv (don't-cache / fetch-volatile) 128-bit load: does NOT allocate in L2,
// unlike __ldcs (evict-first, which still allocates). The 256MB adjacency
// stream has zero reuse, so bypassing L2 allocation keeps the 96KB accumulator
// lines resident — atomics then RMW in L2 instead of DRAM.
__device__ __forceinline__ int4 ldcv_int4(const int4* p) {
    int4 v;
    asm volatile("ld.global.cv.v4.s32 {%0,%1,%2,%3}, [%4];"
                 : "=r"(v.x), "=r"(v.y), "=r"(v.z), "=r"(v.w) : "l"(p));
    return v;
}

// Row-per-warp scan (R11 structure — best measured main) with L2-bypassing
// adjacency loads. Each warp owns 1024 contiguous int4 quads (half a row at
// N=8192): row index, outs[i], targets[i], expf, pack computed ONCE per warp.
__global__ void __launch_bounds__(256) main_kernel(
    const int4* __restrict__ adj,
    const float* __restrict__ outs,
    const int* __restrict__ tgt,
    int rowShift)                          // log2(quads per row)
{
    const int  gtid  = blockIdx.x * blockDim.x + threadIdx.x;
    const int  gwarp = gtid >> 5;
    const int  lane  = gtid & 31;

    const long long quadBase = (long long)gwarp << 10;          // 1024 quads/warp
    const int i      = (int)(quadBase >> rowShift);             // row (warp-uniform)
    const int cqBase = (int)(quadBase & ((1 << rowShift) - 1)); // quad offset in row

    const float o    = __ldg(&outs[i]);                         // broadcast loads
    const int   p    = (__ldg(&tgt[i]) != 0) ? 1 : 0;
    const float e    = expf(o);
    const int   pack = 1 + (p << 16);

    #pragma unroll
    for (int jb = 0; jb < 4; jb++) {
        int4 vv[8];
        #pragma unroll
        for (int u = 0; u < 8; u++)
            vv[u] = ldcv_int4(&adj[quadBase + (jb * 8 + u) * 32 + lane]);

        #pragma unroll
        for (int u = 0; u < 8; u++) {
            int4 v = vv[u];
            if ((v.x | v.y | v.z | v.w) == 0) continue;         // ~98.5% of quads

            int c = (cqBase + (jb * 8 + u) * 32 + lane) << 2;   // first column
            #pragma unroll
            for (int w = 0; w < 4; w++) {
                int val = (w == 0) ? v.x : (w == 1) ? v.y : (w == 2) ? v.z : v.w;
                int cc = c + w;
                if (val != 0 && cc != i) {
                    int side = (i < cc) ? 0 : 1;  // 0 = lower (i < k), 1 = upper
                    atomicAdd(&g_cntpack[side][cc], pack);
                    atomicAdd(&g_sumexp[side][cc], e);
                    if (p) atomicAdd(&g_poslog[side][cc], o);
                }
            }
        }
    }
}

// Per-column contribution: 6 independent loads (L2-resident now that the scan
// bypasses L2), compute, overwrite g_contrib[c], then clean the accumulators
// (same thread owns read + clean -> race-free).
__global__ void __launch_bounds__(256) contrib_kernel(int N) {
    int c = blockIdx.x * blockDim.x + threadIdx.x;
    if (c >= N) return;

    int   pack0 = g_cntpack[0][c], pack1 = g_cntpack[1][c];
    float se0 = g_sumexp[0][c], se1 = g_sumexp[1][c];
    float pl0 = g_poslog[0][c], pl1 = g_poslog[1][c];

    int cnt0 = pack0 & 0xFFFF, pc0 = pack0 >> 16;
    int cnt1 = pack1 & 0xFFFF, pc1 = pack1 >> 16;

    float v = 0.f;
    if (cnt0 > 0 && pc0 == 1) v += (logf(se0) - pl0) / (float)cnt0;
    if (cnt1 > 0 && pc1 == 1) v += (logf(se1) - pl1) / (float)cnt1;
    g_contrib[c] = v;

    // Self-clean for the next graph replay.
    g_cntpack[0][c] = 0; g_cntpack[1][c] = 0;
    g_sumexp[0][c] = 0.f; g_sumexp[1][c] = 0.f;
    g_poslog[0][c] = 0.f; g_poslog[1][c] = 0.f;
}

// Gather g_contrib over idx entries — ONE gather per thread (duplicates in the
// sorted idx supply multiplicity for free), block-reduce, last block publishes.
__global__ void __launch_bounds__(256) reduce_kernel(
    float* __restrict__ out,
    const int* __restrict__ idx,
    int K)
{
    int t = blockIdx.x * blockDim.x + threadIdx.x;

    float local = 0.f;
    if (t < K) local = g_contrib[__ldg(&idx[t])];

    #pragma unroll
    for (int s = 16; s > 0; s >>= 1)
        local += __shfl_xor_sync(0xFFFFFFFF, local, s);

    __shared__ float warpsum[8];
    int lane = threadIdx.x & 31, wid = threadIdx.x >> 5;
    if (lane == 0) warpsum[wid] = local;
    __syncthreads();
    if (wid == 0) {
        float b = (lane < 8) ? warpsum[lane] : 0.f;
        #pragma unroll
        for (int s = 4; s > 0; s >>= 1)
            b += __shfl_xor_sync(0xFFFFFFFF, b, s);
        if (lane == 0) {
            atomicAdd(&g_res, b);
            __threadfence();
            unsigned d = atomicAdd(&g_done, 1u);
            if (d == gridDim.x - 1) {
                out[0] = atomicExch(&g_res, 0.f);
                g_done = 0;
            }
        }
    }
}

extern "C" void kernel_launch(void* const* d_in, const int* in_sizes, int n_in,
                              void* d_out, int out_size) {
    const float* outs = (const float*)d_in[0];   // outputs  [N] f32
    const int*   tgt  = (const int*)d_in[1];     // targets  [N] i32
    const int*   adj  = (const int*)d_in[2];     // node_adj [N,N] i32
    const int*   idx  = (const int*)d_in[3];     // idx_node [K] i32 (sorted)
    int N = in_sizes[0];
    int K = in_sizes[3];
    float* out = (float*)d_out;

    // quadsPerRow = N/4 is a power of two; rowShift = log2(N/4)
    int rowShift = 0;
    for (int t = N >> 2; t > 1; t >>= 1) rowShift++;

    // Each warp: 1024 quads; each block (8 warps): 8192 quads.
    long long totalQuads = ((long long)N * N) >> 2;
    int blocks = (int)(totalQuads >> 13);        // N=8192 -> 2048 blocks

    main_kernel<<<blocks, 256>>>((const int4*)adj, outs, tgt, rowShift);
    contrib_kernel<<<(N + 255) / 256, 256>>>(N);
    reduce_kernel<<<(K + 255) / 256, 256>>>(out, idx, K);
}

// round 16
// speedup vs baseline: 1.0075x; 1.0075x over previous
#include <cuda_runtime.h>

#define NMAX 8192

// Scratch — zero-initialized at module load; clean_kernel restores zeros after
// every call (stream-ordered after reduce_kernel) so graph replays are clean.
__device__ int      g_cntpack[2][NMAX];   // low 16: cnt, high 16: pos_cnt
__device__ float    g_sumexp[2][NMAX];    // sum of exp(out[i]) over mask
__device__ float    g_poslog[2][NMAX];    // sum of out[i] over mask & pos
__device__ float    g_res;                // cross-block partial sum
__device__ unsigned g_done;               // block-completion counter

// Row-per-warp scan (locked R11 configuration — best measured at 44.8us over
// six structural variants; ~6 TB/s is this pattern's ceiling). Each warp owns
// 1024 contiguous int4 quads (half a row at N=8192): row index, outs[i],
// targets[i], expf, pack computed ONCE per warp (lane-uniform). Fully
// coalesced LDG.128, front-batched x8.
__global__ void __launch_bounds__(256) main_kernel(
    const int4* __restrict__ adj,
    const float* __restrict__ outs,
    const int* __restrict__ tgt,
    int rowShift)                          // log2(quads per row)
{
    const int  gtid  = blockIdx.x * blockDim.x + threadIdx.x;
    const int  gwarp = gtid >> 5;
    const int  lane  = gtid & 31;

    const long long quadBase = (long long)gwarp << 10;          // 1024 quads/warp
    const int i      = (int)(quadBase >> rowShift);             // row (warp-uniform)
    const int cqBase = (int)(quadBase & ((1 << rowShift) - 1)); // quad offset in row

    const float o    = __ldg(&outs[i]);                         // broadcast loads
    const int   p    = (__ldg(&tgt[i]) != 0) ? 1 : 0;
    const float e    = expf(o);
    const int   pack = 1 + (p << 16);

    #pragma unroll
    for (int jb = 0; jb < 4; jb++) {
        int4 vv[8];
        #pragma unroll
        for (int u = 0; u < 8; u++)
            vv[u] = __ldg(&adj[quadBase + (jb * 8 + u) * 32 + lane]);

        #pragma unroll
        for (int u = 0; u < 8; u++) {
            int4 v = vv[u];
            if ((v.x | v.y | v.z | v.w) == 0) continue;         // ~98.5% of quads

            int c = (cqBase + (jb * 8 + u) * 32 + lane) << 2;   // first column
            #pragma unroll
            for (int w = 0; w < 4; w++) {
                int val = (w == 0) ? v.x : (w == 1) ? v.y : (w == 2) ? v.z : v.w;
                int cc = c + w;
                if (val != 0 && cc != i) {
                    int side = (i < cc) ? 0 : 1;  // 0 = lower (i < k), 1 = upper
                    atomicAdd(&g_cntpack[side][cc], pack);
                    atomicAdd(&g_sumexp[side][cc], e);
                    if (p) atomicAdd(&g_poslog[side][cc], o);
                }
            }
        }
    }
}

// Direct reduce: thread t (t<K) computes the contribution of column idx[t]
// straight from the accumulators (duplicate idx entries recompute — cheap) in
// ONE flat memory round-trip: idx load, then 6 independent column loads.
// Block-reduce, last block publishes out[0]. No intermediate contrib array.
__global__ void __launch_bounds__(256) reduce_kernel(
    float* __restrict__ out,
    const int* __restrict__ idx,
    int K)
{
    int t = blockIdx.x * blockDim.x + threadIdx.x;

    float local = 0.f;
    if (t < K) {
        int c = __ldg(&idx[t]);

        int   pack0 = g_cntpack[0][c], pack1 = g_cntpack[1][c];
        float se0 = g_sumexp[0][c], se1 = g_sumexp[1][c];
        float pl0 = g_poslog[0][c], pl1 = g_poslog[1][c];

        int cnt0 = pack0 & 0xFFFF, pc0 = pack0 >> 16;
        int cnt1 = pack1 & 0xFFFF, pc1 = pack1 >> 16;

        if (cnt0 > 0 && pc0 == 1) local += (logf(se0) - pl0) / (float)cnt0;
        if (cnt1 > 0 && pc1 == 1) local += (logf(se1) - pl1) / (float)cnt1;
    }

    #pragma unroll
    for (int s = 16; s > 0; s >>= 1)
        local += __shfl_xor_sync(0xFFFFFFFF, local, s);

    __shared__ float warpsum[8];
    int lane = threadIdx.x & 31, wid = threadIdx.x >> 5;
    if (lane == 0) warpsum[wid] = local;
    __syncthreads();
    if (wid == 0) {
        float b = (lane < 8) ? warpsum[lane] : 0.f;
        #pragma unroll
        for (int s = 4; s > 0; s >>= 1)
            b += __shfl_xor_sync(0xFFFFFFFF, b, s);
        if (lane == 0) {
            atomicAdd(&g_res, b);
            __threadfence();
            unsigned d = atomicAdd(&g_done, 1u);
            if (d == gridDim.x - 1) {
                out[0] = atomicExch(&g_res, 0.f);
                g_done = 0;
            }
        }
    }
}

// Pure-store cleanup (stream-ordered AFTER reduce_kernel, so no race with its
// reads). No loads, no chains — fire-and-forget zeros for the next replay.
__global__ void __launch_bounds__(256) clean_kernel(int N) {
    int t = blockIdx.x * blockDim.x + threadIdx.x;
    if (t < N) {
        g_cntpack[0][t] = 0; g_cntpack[1][t] = 0;
        g_sumexp[0][t] = 0.f; g_sumexp[1][t] = 0.f;
        g_poslog[0][t] = 0.f; g_poslog[1][t] = 0.f;
    }
}

extern "C" void kernel_launch(void* const* d_in, const int* in_sizes, int n_in,
                              void* d_out, int out_size) {
    const float* outs = (const float*)d_in[0];   // outputs  [N] f32
    const int*   tgt  = (const int*)d_in[1];     // targets  [N] i32
    const int*   adj  = (const int*)d_in[2];     // node_adj [N,N] i32
    const int*   idx  = (const int*)d_in[3];     // idx_node [K] i32 (sorted)
    int N = in_sizes[0];
    int K = in_sizes[3];
    float* out = (float*)d_out;

    // quadsPerRow = N/4 is a power of two; rowShift = log2(N/4)
    int rowShift = 0;
    for (int t = N >> 2; t > 1; t >>= 1) rowShift++;

    // Each warp: 1024 quads; each block (8 warps): 8192 quads.
    long long totalQuads = ((long long)N * N) >> 2;
    int blocks = (int)(totalQuads >> 13);        // N=8192 -> 2048 blocks

    main_kernel<<<blocks, 256>>>((const int4*)adj, outs, tgt, rowShift);
    reduce_kernel<<<(K + 255) / 256, 256>>>(out, idx, K);
    clean_kernel<<<(N + 255) / 256, 256>>>(N);
}